// round 15
// baseline (speedup 1.0000x reference)
#include <cuda_runtime.h>
#include <cstdint>
#include <cstddef>

#define DI __device__ __forceinline__

// ---------------------------------------------------------------------------
// Problem constants
// ---------------------------------------------------------------------------
namespace {
constexpr int B_   = 64;
constexpr int S_   = 2048;
constexpr int F_   = 40;
constexpr int EMB_ = 128;
constexpr int HID_ = 256;
constexpr int G_   = 4 * HID_;             // 1024 gate rows
constexpr long long MS = (long long)B_ * S_;   // 131072 flattened rows

// Recurrence: 16 clusters x 8 CTAs, 4 batches per cluster as 2 pairs.
constexpr int CLU  = 8;
constexpr int UPC  = HID_ / CLU;           // 32 units per CTA
constexpr int ROWS = 4 * UPC;              // 128 gate rows per CTA
constexpr int BPC  = 4;
constexpr int NTHR = 512;                  // 128 rows x 4 k-chunks
constexpr int NKS  = 4;
constexpr int KC   = HID_ / NKS;           // 64 floats per chunk
constexpr int QN   = KC / 4;               // 16 x 16B loads per chunk
}

// ---------------------------------------------------------------------------
// Scratch (device globals: no runtime allocation allowed)
// ---------------------------------------------------------------------------
__device__ float g_gx[(size_t)MS * G_];     // 536 MB gate preactivations
__device__ float g_hs[(size_t)MS * HID_];   // 134 MB hidden states
__device__ float g_Wc[G_ * F_];             // fused W_ih0 @ W_in
__device__ float g_b0[G_];
__device__ float g_b1[G_];

// ---------------------------------------------------------------------------
// f32x2 helpers (packed dual-FMA; ptxas won't emit from C++)
// ---------------------------------------------------------------------------
DI void ffma2(unsigned long long& acc, unsigned long long a, unsigned long long b) {
    asm("fma.rn.f32x2 %0, %1, %2, %0;" : "+l"(acc) : "l"(a), "l"(b));
}
DI unsigned long long dup2(float x) {
    unsigned long long d;
    unsigned u = __float_as_uint(x);
    asm("mov.b64 %0, {%1, %1};" : "=l"(d) : "r"(u));
    return d;
}
DI float lo2(unsigned long long v) { return __uint_as_float((unsigned)v); }
DI float hi2(unsigned long long v) { return __uint_as_float((unsigned)(v >> 32)); }

DI uint32_t s2u(const void* p) {
    uint32_t a;
    asm("{ .reg .u64 t; cvta.to.shared.u64 t, %1; cvt.u32.u64 %0, t; }"
        : "=r"(a) : "l"(p));
    return a;
}
DI void cluster_sync() {
    asm volatile("barrier.cluster.arrive.aligned;" ::: "memory");
    asm volatile("barrier.cluster.wait.aligned;" ::: "memory");
}
DI void cluster_arrive() {
    asm volatile("barrier.cluster.arrive.aligned;" ::: "memory");
}
DI void cluster_wait() {
    asm volatile("barrier.cluster.wait.aligned;" ::: "memory");
}
DI void st_cluster_v4(uint32_t local_addr, uint32_t rank,
                      float a, float b, float c, float d) {
    asm volatile(
        "{\n\t.reg .b32 ra;\n\t"
        "mapa.shared::cluster.u32 ra, %0, %1;\n\t"
        "st.shared::cluster.v4.f32 [ra], {%2, %3, %4, %5};\n\t}"
        :: "r"(local_addr), "r"(rank), "f"(a), "f"(b), "f"(c), "f"(d) : "memory");
}

// Fast activations: EX2/RCP approx, saturation-safe at +/-inf.
DI float fex2(float x) { float y; asm("ex2.approx.f32 %0, %1;" : "=f"(y) : "f"(x)); return y; }
DI float frcp(float x) { float y; asm("rcp.approx.f32 %0, %1;" : "=f"(y) : "f"(x)); return y; }
constexpr float LOG2E_ = 1.4426950408889634f;
DI float sigf(float x)     { return frcp(1.f + fex2(-x * LOG2E_)); }
DI float tanhfast(float x) { return 1.f - 2.f * frcp(1.f + fex2(x * (2.f * LOG2E_))); }

// ---------------------------------------------------------------------------
// Prep: Wc = W_ih0 @ W_in  (1024 x 40), fused biases
// ---------------------------------------------------------------------------
__global__ void prep_kernel(const float* __restrict__ Wih0, const float* __restrict__ Win,
                            const float* __restrict__ bin,
                            const float* __restrict__ bih0, const float* __restrict__ bhh0,
                            const float* __restrict__ bih1, const float* __restrict__ bhh1) {
    int idx = blockIdx.x * blockDim.x + threadIdx.x;
    if (idx < G_ * F_) {
        int g = idx / F_, f = idx % F_;
        float s = 0.f;
        #pragma unroll 8
        for (int e = 0; e < EMB_; e++) s += Wih0[g * EMB_ + e] * Win[e * F_ + f];
        g_Wc[idx] = s;
    }
    if (idx < G_) {
        float s = bih0[idx] + bhh0[idx];
        #pragma unroll 8
        for (int e = 0; e < EMB_; e++) s += Wih0[idx * EMB_ + e] * bin[e];
        g_b0[idx] = s;
        g_b1[idx] = bih1[idx] + bhh1[idx];
    }
}

// No-op kernel: keeps the ncu capture slot aligned on lstm_rec.
__global__ void noop_kernel() {}

// ---------------------------------------------------------------------------
// GEMM: C[M][N] = A[M][K] @ Bt[N][K] + bias[N]  (R6-exact, proven)
// ---------------------------------------------------------------------------
__global__ __launch_bounds__(256) void gemm_bias_f32(
    const float* __restrict__ A, const float* __restrict__ Bt,
    const float* __restrict__ bias, float* __restrict__ C, int K, int N) {
    __shared__ float As[8][128];
    __shared__ float Bs[8][128];

    const int tid = threadIdx.x;
    const int m0 = blockIdx.y * 128, n0 = blockIdx.x * 128;
    const int lr = tid >> 1, lq = tid & 1;
    const int ty = tid >> 4, tx = tid & 15;

    unsigned long long acc[4][8];
    #pragma unroll
    for (int i = 0; i < 4; i++)
        #pragma unroll
        for (int j = 0; j < 8; j++) acc[i][j] = 0ull;

    for (int kc = 0; kc < K; kc += 8) {
        float4 av = *(const float4*)(A + (size_t)(m0 + lr) * K + kc + lq * 4);
        float4 bv = *(const float4*)(Bt + (size_t)(n0 + lr) * K + kc + lq * 4);
        __syncthreads();
        As[lq * 4 + 0][lr] = av.x; As[lq * 4 + 1][lr] = av.y;
        As[lq * 4 + 2][lr] = av.z; As[lq * 4 + 3][lr] = av.w;
        Bs[lq * 4 + 0][lr] = bv.x; Bs[lq * 4 + 1][lr] = bv.y;
        Bs[lq * 4 + 2][lr] = bv.z; Bs[lq * 4 + 3][lr] = bv.w;
        __syncthreads();
        #pragma unroll
        for (int k = 0; k < 8; k++) {
            ulonglong2 a01 = *(const ulonglong2*)&As[k][ty * 8];
            ulonglong2 a23 = *(const ulonglong2*)&As[k][ty * 8 + 4];
            float4 bl = *(const float4*)&Bs[k][tx * 8];
            float4 bh = *(const float4*)&Bs[k][tx * 8 + 4];
            unsigned long long ap[4] = { a01.x, a01.y, a23.x, a23.y };
            unsigned long long bd[8] = { dup2(bl.x), dup2(bl.y), dup2(bl.z), dup2(bl.w),
                                         dup2(bh.x), dup2(bh.y), dup2(bh.z), dup2(bh.w) };
            #pragma unroll
            for (int mp = 0; mp < 4; mp++)
                #pragma unroll
                for (int j = 0; j < 8; j++)
                    ffma2(acc[mp][j], ap[mp], bd[j]);
        }
    }

    float bvv[8];
    #pragma unroll
    for (int j = 0; j < 8; j++) bvv[j] = bias[n0 + tx * 8 + j];

    #pragma unroll
    for (int mp = 0; mp < 4; mp++) {
        int m = m0 + ty * 8 + mp * 2;
        float4 r0a = { lo2(acc[mp][0]) + bvv[0], lo2(acc[mp][1]) + bvv[1],
                       lo2(acc[mp][2]) + bvv[2], lo2(acc[mp][3]) + bvv[3] };
        float4 r0b = { lo2(acc[mp][4]) + bvv[4], lo2(acc[mp][5]) + bvv[5],
                       lo2(acc[mp][6]) + bvv[6], lo2(acc[mp][7]) + bvv[7] };
        float4 r1a = { hi2(acc[mp][0]) + bvv[0], hi2(acc[mp][1]) + bvv[1],
                       hi2(acc[mp][2]) + bvv[2], hi2(acc[mp][3]) + bvv[3] };
        float4 r1b = { hi2(acc[mp][4]) + bvv[4], hi2(acc[mp][5]) + bvv[5],
                       hi2(acc[mp][6]) + bvv[6], hi2(acc[mp][7]) + bvv[7] };
        float* c0 = C + (size_t)m * N + n0 + tx * 8;
        float* c1 = c0 + N;
        *(float4*)c0 = r0a;       *(float4*)(c0 + 4) = r0b;
        *(float4*)c1 = r1a;       *(float4*)(c1 + 4) = r1b;
    }
}

// ---------------------------------------------------------------------------
// LSTM recurrence v8: split cluster barrier + interleaved batch pairs.
// Pairs A={0,1}, B={2,3} alternate per iteration (2*S iterations).
// Per iter: dot(2 batches) -> syncthreads -> update+publish -> WAIT -> ARRIVE.
// wait#(k+1) completes on arrives issued at end of iter k-1 => one full iter
// of compute hides barrier propagation/skew. Strict A,W alternation (legal).
// sRed double-buffered by iter parity; h buffers [pair][t&1][2][HID].
// ---------------------------------------------------------------------------
__global__ void __cluster_dims__(CLU, 1, 1) __launch_bounds__(NTHR, 1)
lstm_rec_kernel(const float* __restrict__ Whh, const float* __restrict__ gx,
                float* __restrict__ hs) {
    __shared__ float sH[2][2][2][HID_];        // [pair][parity][batch-in-pair][HID]
    __shared__ float sRed[2][NKS][ROWS][2];    // [iter&1][ks][row][batch-in-pair]

    const int tid  = threadIdx.x;
    const int rank = blockIdx.x % CLU;
    const int grp  = blockIdx.x / CLU;
    const int r    = tid & 127;
    const int ks   = tid >> 7;
    const int gate = r >> 5;
    const int u    = r & 31;
    const int grow = gate * HID_ + rank * UPC + u;

    // W chunk into registers: 64 floats = 32 packed pairs
    unsigned long long w[KC / 2];
    {
        const float4* src = (const float4*)(Whh + (size_t)grow * HID_ + ks * KC);
        #pragma unroll
        for (int i = 0; i < QN; i++) {
            float4 v = src[i];
            ulonglong2 p = *(const ulonglong2*)&v;
            w[2 * i]     = p.x;
            w[2 * i + 1] = p.y;
        }
    }

    for (int i = tid; i < 2 * 2 * 2 * HID_; i += NTHR) (&sH[0][0][0][0])[i] = 0.f;
    __syncthreads();
    cluster_sync();     // zeroed buffers visible cluster-wide

    // Update-thread state (tid < 128): unit uu, batch bb (0..3).
    const int uu = tid >> 2, bb = tid & 3;
    const int myPair = bb >> 1, bbl = bb & 1;
    float c = 0.f;
    float gxn[4];
    const float* gxbase = gx + (size_t)(grp * BPC + bb) * S_ * G_ + rank * UPC + uu;
    if (tid < 128) {
        #pragma unroll
        for (int g = 0; g < 4; g++) gxn[g] = __ldg(gxbase + g * HID_);
    }

    cluster_arrive();    // A#1 — opens the pipeline

    for (int k = 0; k < 2 * S_; k++) {
        const int p    = k & 1;        // pair advancing this iter
        const int t    = k >> 1;       // its timestep
        const int par  = t & 1;        // write parity
        const int kpar = k & 1;        // sRed parity (alternates per iter)

        // ---- dot: pair p's 2 batches over h[p][par^1] ----
        const float* hp = &sH[p][par ^ 1][0][0];
        const ulonglong2* hA = (const ulonglong2*)(hp + ks * KC);
        const ulonglong2* hB = (const ulonglong2*)(hp + HID_ + ks * KC);
        unsigned long long s0 = 0ull, s1 = 0ull, s2 = 0ull, s3 = 0ull;
        #pragma unroll
        for (int q = 0; q < QN; q++) {
            ulonglong2 xA = hA[q];
            ulonglong2 xB = hB[q];
            ffma2(s0, w[2 * q],     xA.x);
            ffma2(s1, w[2 * q + 1], xA.y);
            ffma2(s2, w[2 * q],     xB.x);
            ffma2(s3, w[2 * q + 1], xB.y);
        }
        float2 pv = { (lo2(s0) + hi2(s0)) + (lo2(s1) + hi2(s1)),
                      (lo2(s2) + hi2(s2)) + (lo2(s3) + hi2(s3)) };
        *(float2*)&sRed[kpar][ks][r][0] = pv;
        __syncthreads();

        // ---- cell update for the active pair's 64 threads ----
        if (tid < 128 && myPair == p) {
            float gates[4];
            #pragma unroll
            for (int g = 0; g < 4; g++) {
                int rr = g * 32 + uu;
                gates[g] = gxn[g] + sRed[kpar][0][rr][bbl] + sRed[kpar][1][rr][bbl]
                                  + sRed[kpar][2][rr][bbl] + sRed[kpar][3][rr][bbl];
            }
            {   // prefetch next step's gx (2-iter slack), clamped (R7 lesson)
                int tn = (t + 1 < S_) ? (t + 1) : (S_ - 1);
                const float* gp = gxbase + (size_t)tn * G_;
                #pragma unroll
                for (int g = 0; g < 4; g++) gxn[g] = __ldg(gp + g * HID_);
            }
            float gi = sigf(gates[0]);
            float gf = sigf(gates[1]);
            float gg = tanhfast(gates[2]);
            float go = sigf(gates[3]);
            c = gf * c + gi * gg;
            float h = go * tanhfast(c);

            // pack 4 consecutive units (same batch) via shfl within active lanes
            const unsigned mask = p ? 0xCCCCCCCCu : 0x33333333u;
            float h1 = __shfl_down_sync(mask, h, 4);
            float h2 = __shfl_down_sync(mask, h, 8);
            float h3 = __shfl_down_sync(mask, h, 12);
            if ((uu & 3) == 0) {
                uint32_t loc = s2u(&sH[p][par][bbl][rank * UPC + uu]);
                #pragma unroll
                for (int pr = 0; pr < CLU; pr++)
                    st_cluster_v4(loc, (uint32_t)pr, h, h1, h2, h3);
            }
            hs[((size_t)(grp * BPC + bb) * S_ + t) * HID_ + rank * UPC + uu] = h;
        }

        cluster_wait();      // completes phase k+1 (arrives from end of iter k-1)
        cluster_arrive();    // opens phase k+2 (releases this iter's publishes)
    }
    cluster_sync();   // final rendezvous before any CTA tears down its smem
}

// ---------------------------------------------------------------------------
// Output projection: out[m] = dot(hs[m], W_out) + b_out  (1 warp per row)
// ---------------------------------------------------------------------------
__global__ __launch_bounds__(256) void outproj_kernel(
    const float* __restrict__ hsbuf, const float* __restrict__ Wout,
    const float* __restrict__ bout, float* __restrict__ out) {
    const long long w = ((long long)blockIdx.x * blockDim.x + threadIdx.x) >> 5;
    const int lane = threadIdx.x & 31;
    if (w >= MS) return;
    const float4* hp = (const float4*)(hsbuf + (size_t)w * HID_);
    const float4* wp = (const float4*)Wout;
    float s = 0.f;
    #pragma unroll
    for (int q = 0; q < 2; q++) {
        float4 h = hp[lane + q * 32];
        float4 ww = wp[lane + q * 32];
        s += h.x * ww.x + h.y * ww.y + h.z * ww.z + h.w * ww.w;
    }
    #pragma unroll
    for (int off = 16; off; off >>= 1) s += __shfl_xor_sync(0xFFFFFFFFu, s, off);
    if (lane == 0) out[w] = s + bout[0];
}

// ---------------------------------------------------------------------------
// Launch
// ---------------------------------------------------------------------------
extern "C" void kernel_launch(void* const* d_in, const int* in_sizes, int n_in,
                              void* d_out, int out_size) {
    const float* in_states = (const float*)d_in[0];
    const float* W_in  = (const float*)d_in[1];
    const float* b_in  = (const float*)d_in[2];
    const float* W_ih0 = (const float*)d_in[3];
    const float* W_hh0 = (const float*)d_in[4];
    const float* b_ih0 = (const float*)d_in[5];
    const float* b_hh0 = (const float*)d_in[6];
    const float* W_ih1 = (const float*)d_in[7];
    const float* W_hh1 = (const float*)d_in[8];
    const float* b_ih1 = (const float*)d_in[9];
    const float* b_hh1 = (const float*)d_in[10];
    const float* W_out = (const float*)d_in[11];
    const float* b_out = (const float*)d_in[12];
    float* out = (float*)d_out;

    float *gx = nullptr, *hsb = nullptr, *Wc = nullptr, *b0 = nullptr, *b1 = nullptr;
    cudaGetSymbolAddress((void**)&gx,  g_gx);
    cudaGetSymbolAddress((void**)&hsb, g_hs);
    cudaGetSymbolAddress((void**)&Wc,  g_Wc);
    cudaGetSymbolAddress((void**)&b0,  g_b0);
    cudaGetSymbolAddress((void**)&b1,  g_b1);

    // 1) fused weights/biases
    prep_kernel<<<(G_ * F_ + 255) / 256, 256>>>(W_ih0, W_in, b_in, b_ih0, b_hh0, b_ih1, b_hh1);

    dim3 ggrid(G_ / 128, (unsigned)(MS / 128));   // (8, 1024)

    // 2) gx0 = in_states @ Wc^T + b0     (K = 40)
    gemm_bias_f32<<<ggrid, 256>>>(in_states, Wc, b0, gx, F_, G_);

    // keeps ncu capture slot on the recurrence kernel
    noop_kernel<<<1, 32>>>();

    // 3) layer-0 recurrence -> hs
    lstm_rec_kernel<<<16 * CLU, NTHR>>>(W_hh0, gx, hsb);

    // 4) gx1 = hs @ W_ih1^T + b1        (K = 256)
    gemm_bias_f32<<<ggrid, 256>>>(hsb, W_ih1, b1, gx, HID_, G_);

    // 5) layer-1 recurrence -> hs
    lstm_rec_kernel<<<16 * CLU, NTHR>>>(W_hh1, gx, hsb);

    // 6) output projection
    outproj_kernel<<<(unsigned)(MS / 8), 256>>>(hsb, W_out, b_out, out);
}

// round 17
// speedup vs baseline: 1.1934x; 1.1934x over previous
#include <cuda_runtime.h>
#include <cstdint>
#include <cstddef>

#define DI __device__ __forceinline__

// ---------------------------------------------------------------------------
// Problem constants
// ---------------------------------------------------------------------------
namespace {
constexpr int B_   = 64;
constexpr int S_   = 2048;
constexpr int F_   = 40;
constexpr int EMB_ = 128;
constexpr int HID_ = 256;
constexpr int G_   = 4 * HID_;             // 1024 gate rows
constexpr long long MS = (long long)B_ * S_;   // 131072 flattened rows

// Recurrence geometry: 16 clusters x 8 CTAs, 4 batches per cluster (R6 best).
constexpr int CLU  = 8;
constexpr int UPC  = HID_ / CLU;           // 32 units per CTA
constexpr int ROWS = 4 * UPC;              // 128 gate rows per CTA
constexpr int BPC  = 4;
constexpr int NTHR = 512;                  // 128 rows x 4 k-chunks
constexpr int NKS  = 4;
constexpr int KC   = HID_ / NKS;           // 64 floats per chunk
constexpr int QN   = KC / 4;               // 16 x 16B loads per chunk

constexpr int RING = 4;                    // gx ring slots
constexpr int LA   = 3;                    // prefetch lookahead (steps)
}

// ---------------------------------------------------------------------------
// Scratch (device globals: no runtime allocation allowed)
// ---------------------------------------------------------------------------
__device__ float g_gx[(size_t)MS * G_];     // 536 MB gate preactivations
__device__ float g_hs[(size_t)MS * HID_];   // 134 MB hidden states
__device__ float g_Wc[G_ * F_];             // fused W_ih0 @ W_in
__device__ float g_b0[G_];
__device__ float g_b1[G_];

// ---------------------------------------------------------------------------
// f32x2 helpers (packed dual-FMA; ptxas won't emit from C++)
// ---------------------------------------------------------------------------
DI void ffma2(unsigned long long& acc, unsigned long long a, unsigned long long b) {
    asm("fma.rn.f32x2 %0, %1, %2, %0;" : "+l"(acc) : "l"(a), "l"(b));
}
DI unsigned long long dup2(float x) {
    unsigned long long d;
    unsigned u = __float_as_uint(x);
    asm("mov.b64 %0, {%1, %1};" : "=l"(d) : "r"(u));
    return d;
}
DI float lo2(unsigned long long v) { return __uint_as_float((unsigned)v); }
DI float hi2(unsigned long long v) { return __uint_as_float((unsigned)(v >> 32)); }

DI uint32_t s2u(const void* p) {
    uint32_t a;
    asm("{ .reg .u64 t; cvta.to.shared.u64 t, %1; cvt.u32.u64 %0, t; }"
        : "=r"(a) : "l"(p));
    return a;
}
DI void cluster_sync() {
    asm volatile("barrier.cluster.arrive.aligned;" ::: "memory");
    asm volatile("barrier.cluster.wait.aligned;" ::: "memory");
}
DI void st_cluster_f32(uint32_t local_addr, uint32_t rank, float v) {
    asm volatile(
        "{\n\t.reg .b32 ra;\n\t"
        "mapa.shared::cluster.u32 ra, %0, %1;\n\t"
        "st.shared::cluster.f32 [ra], %2;\n\t}"
        :: "r"(local_addr), "r"(rank), "f"(v) : "memory");
}

// Fast activations: EX2/RCP approx, saturation-safe at +/-inf.
DI float fex2(float x) { float y; asm("ex2.approx.f32 %0, %1;" : "=f"(y) : "f"(x)); return y; }
DI float frcp(float x) { float y; asm("rcp.approx.f32 %0, %1;" : "=f"(y) : "f"(x)); return y; }
constexpr float LOG2E_ = 1.4426950408889634f;
DI float sigf(float x)     { return frcp(1.f + fex2(-x * LOG2E_)); }
DI float tanhfast(float x) { return 1.f - 2.f * frcp(1.f + fex2(x * (2.f * LOG2E_))); }

// ---------------------------------------------------------------------------
// Prep: Wc = W_ih0 @ W_in  (1024 x 40), fused biases
// ---------------------------------------------------------------------------
__global__ void prep_kernel(const float* __restrict__ Wih0, const float* __restrict__ Win,
                            const float* __restrict__ bin,
                            const float* __restrict__ bih0, const float* __restrict__ bhh0,
                            const float* __restrict__ bih1, const float* __restrict__ bhh1) {
    int idx = blockIdx.x * blockDim.x + threadIdx.x;
    if (idx < G_ * F_) {
        int g = idx / F_, f = idx % F_;
        float s = 0.f;
        #pragma unroll 8
        for (int e = 0; e < EMB_; e++) s += Wih0[g * EMB_ + e] * Win[e * F_ + f];
        g_Wc[idx] = s;
    }
    if (idx < G_) {
        float s = bih0[idx] + bhh0[idx];
        #pragma unroll 8
        for (int e = 0; e < EMB_; e++) s += Wih0[idx * EMB_ + e] * bin[e];
        g_b0[idx] = s;
        g_b1[idx] = bih1[idx] + bhh1[idx];
    }
}

// No-op kernel: keeps the ncu capture slot aligned on lstm_rec.
__global__ void noop_kernel() {}

// ---------------------------------------------------------------------------
// GEMM: C[M][N] = A[M][K] @ Bt[N][K] + bias[N]  (R6-exact, proven)
// ---------------------------------------------------------------------------
__global__ __launch_bounds__(256) void gemm_bias_f32(
    const float* __restrict__ A, const float* __restrict__ Bt,
    const float* __restrict__ bias, float* __restrict__ C, int K, int N) {
    __shared__ float As[8][128];
    __shared__ float Bs[8][128];

    const int tid = threadIdx.x;
    const int m0 = blockIdx.y * 128, n0 = blockIdx.x * 128;
    const int lr = tid >> 1, lq = tid & 1;
    const int ty = tid >> 4, tx = tid & 15;

    unsigned long long acc[4][8];
    #pragma unroll
    for (int i = 0; i < 4; i++)
        #pragma unroll
        for (int j = 0; j < 8; j++) acc[i][j] = 0ull;

    for (int kc = 0; kc < K; kc += 8) {
        float4 av = *(const float4*)(A + (size_t)(m0 + lr) * K + kc + lq * 4);
        float4 bv = *(const float4*)(Bt + (size_t)(n0 + lr) * K + kc + lq * 4);
        __syncthreads();
        As[lq * 4 + 0][lr] = av.x; As[lq * 4 + 1][lr] = av.y;
        As[lq * 4 + 2][lr] = av.z; As[lq * 4 + 3][lr] = av.w;
        Bs[lq * 4 + 0][lr] = bv.x; Bs[lq * 4 + 1][lr] = bv.y;
        Bs[lq * 4 + 2][lr] = bv.z; Bs[lq * 4 + 3][lr] = bv.w;
        __syncthreads();
        #pragma unroll
        for (int k = 0; k < 8; k++) {
            ulonglong2 a01 = *(const ulonglong2*)&As[k][ty * 8];
            ulonglong2 a23 = *(const ulonglong2*)&As[k][ty * 8 + 4];
            float4 bl = *(const float4*)&Bs[k][tx * 8];
            float4 bh = *(const float4*)&Bs[k][tx * 8 + 4];
            unsigned long long ap[4] = { a01.x, a01.y, a23.x, a23.y };
            unsigned long long bd[8] = { dup2(bl.x), dup2(bl.y), dup2(bl.z), dup2(bl.w),
                                         dup2(bh.x), dup2(bh.y), dup2(bh.z), dup2(bh.w) };
            #pragma unroll
            for (int mp = 0; mp < 4; mp++)
                #pragma unroll
                for (int j = 0; j < 8; j++)
                    ffma2(acc[mp][j], ap[mp], bd[j]);
        }
    }

    float bvv[8];
    #pragma unroll
    for (int j = 0; j < 8; j++) bvv[j] = bias[n0 + tx * 8 + j];

    #pragma unroll
    for (int mp = 0; mp < 4; mp++) {
        int m = m0 + ty * 8 + mp * 2;
        float4 r0a = { lo2(acc[mp][0]) + bvv[0], lo2(acc[mp][1]) + bvv[1],
                       lo2(acc[mp][2]) + bvv[2], lo2(acc[mp][3]) + bvv[3] };
        float4 r0b = { lo2(acc[mp][4]) + bvv[4], lo2(acc[mp][5]) + bvv[5],
                       lo2(acc[mp][6]) + bvv[6], lo2(acc[mp][7]) + bvv[7] };
        float4 r1a = { hi2(acc[mp][0]) + bvv[0], hi2(acc[mp][1]) + bvv[1],
                       hi2(acc[mp][2]) + bvv[2], hi2(acc[mp][3]) + bvv[3] };
        float4 r1b = { hi2(acc[mp][4]) + bvv[4], hi2(acc[mp][5]) + bvv[5],
                       hi2(acc[mp][6]) + bvv[6], hi2(acc[mp][7]) + bvv[7] };
        float* c0 = C + (size_t)m * N + n0 + tx * 8;
        float* c1 = c0 + N;
        *(float4*)c0 = r0a;       *(float4*)(c0 + 4) = r0b;
        *(float4*)c1 = r1a;       *(float4*)(c1 + 4) = r1b;
    }
}

// ---------------------------------------------------------------------------
// LSTM recurrence v10: R6-exact sync protocol + smem gx RING BUFFER.
// Warps 4-7 (tid 128..255, idle in R6's update phase) prefetch gx[t+LA] into
// a 4-slot smem ring; update threads read gx via LDS (deterministic 29 cyc),
// removing DRAM-miss jitter from the serial chain / barrier skew.
// Slot audit: at step t update reads slot t&3 while prefetch writes (t+3)&3
// (distinct); write(step t, slot s) -> read(step t+3, slot s) crosses >=3
// __syncthreads/cluster_syncs; writes for t+3 >= S_ are skipped (slot dead).
// ---------------------------------------------------------------------------
__global__ void __cluster_dims__(CLU, 1, 1) __launch_bounds__(NTHR, 1)
lstm_rec_kernel(const float* __restrict__ Whh, const float* __restrict__ gx,
                float* __restrict__ hs) {
    __shared__ float sH[2][BPC][HID_];       // double-buffered hidden state
    __shared__ float sRed[NKS][ROWS][BPC];   // partial sums
    __shared__ float sGx[RING][4][128];      // gx ring: [slot][gate][uu*4+bb]

    const int tid  = threadIdx.x;
    const int rank = blockIdx.x % CLU;
    const int grp  = blockIdx.x / CLU;
    const int r    = tid & 127;
    const int ks   = tid >> 7;
    const int gate = r >> 5;
    const int u    = r & 31;
    const int grow = gate * HID_ + rank * UPC + u;

    // W chunk into registers: 64 floats = 32 packed pairs
    unsigned long long w[KC / 2];
    {
        const float4* src = (const float4*)(Whh + (size_t)grow * HID_ + ks * KC);
        #pragma unroll
        for (int i = 0; i < QN; i++) {
            float4 v = src[i];
            ulonglong2 p = *(const ulonglong2*)&v;
            w[2 * i]     = p.x;
            w[2 * i + 1] = p.y;
        }
    }

    // Prefetch-thread mapping (tid 128..255): mirrors update thread pt.
    const int pt  = tid - 128;               // 0..127
    const int uu2 = pt >> 2, bb2 = pt & 3;
    const float* gxp = gx + (size_t)(grp * BPC + bb2) * S_ * G_ + rank * UPC + uu2;

    // Zero h buffers + prologue ring fill (slots for steps 0..LA-1).
    for (int i = tid; i < 2 * BPC * HID_; i += NTHR) (&sH[0][0][0])[i] = 0.f;
    if (tid >= 128 && tid < 256) {
        #pragma unroll
        for (int s = 0; s < LA; s++) {
            const float* gp = gxp + (size_t)s * G_;
            #pragma unroll
            for (int g = 0; g < 4; g++)
                sGx[s][g][pt] = __ldg(gp + g * HID_);
        }
    }
    __syncthreads();
    cluster_sync();     // zeroed cluster-wide before any peer writes

    // Update-thread state (tid < 128): unit uu, batch bb.
    const int uu = tid >> 2, bb = tid & 3;
    float c = 0.f;

    int cur = 0;
    for (int t = 0; t < S_; t++) {
        // ---- partial dots: two passes of 2 batches ----
        const float* hp = &sH[cur][0][0];
        float red[4];
        #pragma unroll
        for (int bp = 0; bp < 2; bp++) {
            const ulonglong2* hA = (const ulonglong2*)(hp + (2 * bp + 0) * HID_ + ks * KC);
            const ulonglong2* hB = (const ulonglong2*)(hp + (2 * bp + 1) * HID_ + ks * KC);
            unsigned long long s0 = 0ull, s1 = 0ull, s2 = 0ull, s3 = 0ull;
            #pragma unroll
            for (int q = 0; q < QN; q++) {
                ulonglong2 xA = hA[q];
                ulonglong2 xB = hB[q];
                ffma2(s0, w[2 * q],     xA.x);
                ffma2(s1, w[2 * q + 1], xA.y);
                ffma2(s2, w[2 * q],     xB.x);
                ffma2(s3, w[2 * q + 1], xB.y);
            }
            red[2 * bp + 0] = (lo2(s0) + hi2(s0)) + (lo2(s1) + hi2(s1));
            red[2 * bp + 1] = (lo2(s2) + hi2(s2)) + (lo2(s3) + hi2(s3));
        }
        float4 pv = { red[0], red[1], red[2], red[3] };
        *(float4*)&sRed[ks][r][0] = pv;
        __syncthreads();

        // ---- cell update (tid < 128) | gx prefetch (tid 128..255) ----
        if (tid < 128) {
            const int slot = t & (RING - 1);
            float gates[4];
            #pragma unroll
            for (int g = 0; g < 4; g++) {
                int rr = g * 32 + uu;
                gates[g] = sGx[slot][g][tid]
                         + sRed[0][rr][bb] + sRed[1][rr][bb]
                         + sRed[2][rr][bb] + sRed[3][rr][bb];
            }
            float gi = sigf(gates[0]);
            float gf = sigf(gates[1]);
            float gg = tanhfast(gates[2]);
            float go = sigf(gates[3]);
            c = gf * c + gi * gg;
            float h = go * tanhfast(c);

            // scalar DSMEM broadcast to all 8 peers (R6-exact)
            uint32_t loc = s2u(&sH[cur ^ 1][bb][rank * UPC + uu]);
            #pragma unroll
            for (int p = 0; p < CLU; p++)
                st_cluster_f32(loc, (uint32_t)p, h);
            hs[((size_t)(grp * BPC + bb) * S_ + t) * HID_ + rank * UPC + uu] = h;
        } else if (tid < 256) {
            const int tn = t + LA;
            if (tn < S_) {
                const int slot = tn & (RING - 1);
                const float* gp = gxp + (size_t)tn * G_;
                #pragma unroll
                for (int g = 0; g < 4; g++)
                    sGx[slot][g][pt] = __ldg(gp + g * HID_);
            }
        }
        cluster_sync();    // release h writes cluster-wide
        cur ^= 1;
    }
}

// ---------------------------------------------------------------------------
// Output projection: out[m] = dot(hs[m], W_out) + b_out  (1 warp per row)
// ---------------------------------------------------------------------------
__global__ __launch_bounds__(256) void outproj_kernel(
    const float* __restrict__ hsbuf, const float* __restrict__ Wout,
    const float* __restrict__ bout, float* __restrict__ out) {
    const long long w = ((long long)blockIdx.x * blockDim.x + threadIdx.x) >> 5;
    const int lane = threadIdx.x & 31;
    if (w >= MS) return;
    const float4* hp = (const float4*)(hsbuf + (size_t)w * HID_);
    const float4* wp = (const float4*)Wout;
    float s = 0.f;
    #pragma unroll
    for (int q = 0; q < 2; q++) {
        float4 h = hp[lane + q * 32];
        float4 ww = wp[lane + q * 32];
        s += h.x * ww.x + h.y * ww.y + h.z * ww.z + h.w * ww.w;
    }
    #pragma unroll
    for (int off = 16; off; off >>= 1) s += __shfl_xor_sync(0xFFFFFFFFu, s, off);
    if (lane == 0) out[w] = s + bout[0];
}

// ---------------------------------------------------------------------------
// Launch
// ---------------------------------------------------------------------------
extern "C" void kernel_launch(void* const* d_in, const int* in_sizes, int n_in,
                              void* d_out, int out_size) {
    const float* in_states = (const float*)d_in[0];
    const float* W_in  = (const float*)d_in[1];
    const float* b_in  = (const float*)d_in[2];
    const float* W_ih0 = (const float*)d_in[3];
    const float* W_hh0 = (const float*)d_in[4];
    const float* b_ih0 = (const float*)d_in[5];
    const float* b_hh0 = (const float*)d_in[6];
    const float* W_ih1 = (const float*)d_in[7];
    const float* W_hh1 = (const float*)d_in[8];
    const float* b_ih1 = (const float*)d_in[9];
    const float* b_hh1 = (const float*)d_in[10];
    const float* W_out = (const float*)d_in[11];
    const float* b_out = (const float*)d_in[12];
    float* out = (float*)d_out;

    float *gx = nullptr, *hsb = nullptr, *Wc = nullptr, *b0 = nullptr, *b1 = nullptr;
    cudaGetSymbolAddress((void**)&gx,  g_gx);
    cudaGetSymbolAddress((void**)&hsb, g_hs);
    cudaGetSymbolAddress((void**)&Wc,  g_Wc);
    cudaGetSymbolAddress((void**)&b0,  g_b0);
    cudaGetSymbolAddress((void**)&b1,  g_b1);

    // 1) fused weights/biases
    prep_kernel<<<(G_ * F_ + 255) / 256, 256>>>(W_ih0, W_in, b_in, b_ih0, b_hh0, b_ih1, b_hh1);

    dim3 ggrid(G_ / 128, (unsigned)(MS / 128));   // (8, 1024)

    // 2) gx0 = in_states @ Wc^T + b0     (K = 40)
    gemm_bias_f32<<<ggrid, 256>>>(in_states, Wc, b0, gx, F_, G_);

    // keeps ncu capture slot on the recurrence kernel
    noop_kernel<<<1, 32>>>();

    // 3) layer-0 recurrence -> hs
    lstm_rec_kernel<<<16 * CLU, NTHR>>>(W_hh0, gx, hsb);

    // 4) gx1 = hs @ W_ih1^T + b1        (K = 256)
    gemm_bias_f32<<<ggrid, 256>>>(hsb, W_ih1, b1, gx, HID_, G_);

    // 5) layer-1 recurrence -> hs
    lstm_rec_kernel<<<16 * CLU, NTHR>>>(W_hh1, gx, hsb);

    // 6) output projection
    outproj_kernel<<<(unsigned)(MS / 8), 256>>>(hsb, W_out, b_out, out);
}